// round 7
// baseline (speedup 1.0000x reference)
#include <cuda_runtime.h>
#include <cuda_bf16.h>
#include <float.h>

#define N_ROIS 256
#define CCH 256
#define HF 50
#define WF 50
#define PK 7
#define IN_FLAT (CCH * PK * PK)   // 12544
#define HID 2048
#define NLOC 84
#define NCLS 21

// Scratch (allocation-free rule: device globals)
__device__ float g_pooled[N_ROIS * IN_FLAT];   // 12.8 MB
__device__ float g_fc1[N_ROIS * HID];          // 2 MB
__device__ float g_fc2[N_ROIS * HID];          // 2 MB

// ---------------------------------------------------------------------------
// RoIPool. R7 PROBE: qh/qw computed with __fdividef (div.approx.f32) to match
// a reference executed with XLA:GPU's approximate f32 division. roi_h is a
// small integer; for roi_h in {7,14} an approximate divide puts ph*qh exactly
// at integer crossings one ulp off, shifting every bin boundary — the only
// non-IEEE-pinned operation in the whole reference, and the only hypothesis
// that quantitatively reproduces the stable 0.1681788.
// ---------------------------------------------------------------------------
__global__ void roi_pool_kernel(const float* __restrict__ feat,
                                const float* __restrict__ rois,
                                float* __restrict__ out) {
    int m = blockIdx.x;
    int c = threadIdx.x;

    const float* r = rois + m * 5;
    float x1 = rintf(r[1] * 0.0625f);
    float y1 = rintf(r[2] * 0.0625f);
    float x2 = rintf(r[3] * 0.0625f);
    float y2 = rintf(r[4] * 0.0625f);
    float roi_w = fmaxf(x2 - x1 + 1.0f, 1.0f);
    float roi_h = fmaxf(y2 - y1 + 1.0f, 1.0f);
    float qh = __fdividef(roi_h, 7.0f);   // div.approx.f32  <-- R7 probe
    float qw = __fdividef(roi_w, 7.0f);   // div.approx.f32  <-- R7 probe

    const float* fc_ptr = feat + c * (HF * WF);

    for (int ph = 0; ph < PK; ph++) {
        float hs_f = fminf(fmaxf(floorf(__fmul_rn((float)ph, qh)) + y1, 0.0f), (float)HF);
        float he_f = fminf(fmaxf(ceilf(__fmul_rn((float)(ph + 1), qh)) + y1, 0.0f), (float)HF);
        int hs = (int)hs_f, he = (int)he_f;
        for (int pw = 0; pw < PK; pw++) {
            float ws_f = fminf(fmaxf(floorf(__fmul_rn((float)pw, qw)) + x1, 0.0f), (float)WF);
            float we_f = fminf(fmaxf(ceilf(__fmul_rn((float)(pw + 1), qw)) + x1, 0.0f), (float)WF);
            int ws = (int)ws_f, we = (int)we_f;

            float mx;
            if (he <= hs || we <= ws) {
                mx = 0.0f;   // empty bin -> 0 (reference replaces NEG with 0)
            } else {
                mx = -FLT_MAX;
                for (int h = hs; h < he; h++) {
                    const float* rowp = fc_ptr + h * WF;
                    for (int w = ws; w < we; w++)
                        mx = fmaxf(mx, rowp[w]);
                }
            }
            out[((m * CCH + c) * PK + ph) * PK + pw] = mx;
        }
    }
}

// ---------------------------------------------------------------------------
// Deliberately-simple GEMM (frozen from R5/R6 for clean attribution):
// C[M,N] = A[M,K] @ B[K,N] + bias. One thread per column, 16 rows per block.
// ---------------------------------------------------------------------------
__global__ void naive_gemm(const float* __restrict__ A,
                           const float* __restrict__ B,
                           const float* __restrict__ bias,
                           float* __restrict__ C,
                           int M, int N, int K) {
    int n  = blockIdx.x * blockDim.x + threadIdx.x;
    int m0 = blockIdx.y * 16;
    if (n >= N) return;

    float acc[16];
    #pragma unroll
    for (int i = 0; i < 16; i++) acc[i] = 0.0f;

    for (int k = 0; k < K; k++) {
        float b = B[(long)k * N + n];
        #pragma unroll
        for (int i = 0; i < 16; i++)
            acc[i] = fmaf(A[(long)(m0 + i) * K + k], b, acc[i]);
    }

    float bb = bias[n];
    #pragma unroll
    for (int i = 0; i < 16; i++)
        C[(long)(m0 + i) * N + n] = acc[i] + bb;
}

// ---------------------------------------------------------------------------
extern "C" void kernel_launch(void* const* d_in, const int* in_sizes, int n_in,
                              void* d_out, int out_size) {
    // Identify inputs by unique element count (b0/b1 disambiguated by order).
    const float *features = 0, *rois = 0, *W0 = 0, *b0 = 0, *W1 = 0, *b1 = 0,
                *Wcls = 0, *bcls = 0, *Wloc = 0, *bloc = 0;
    for (int i = 0; i < n_in; i++) {
        const float* p = (const float*)d_in[i];
        switch (in_sizes[i]) {
            case 640000:   features = p; break;                 // 1*256*50*50
            case 1280:     rois = p; break;                     // 256*5
            case 25690112: W0 = p; break;                       // 12544*2048
            case 4194304:  W1 = p; break;                       // 2048*2048
            case 43008:    Wcls = p; break;                     // 2048*21
            case 21:       bcls = p; break;
            case 172032:   Wloc = p; break;                     // 2048*84
            case 84:       bloc = p; break;
            case 2048:     if (!b0) b0 = p; else b1 = p; break; // b0 then b1
            default: break;
        }
    }
    float* out = (float*)d_out;

    float* pooled; cudaGetSymbolAddress((void**)&pooled, g_pooled);
    float* fc1;    cudaGetSymbolAddress((void**)&fc1, g_fc1);
    float* fc2;    cudaGetSymbolAddress((void**)&fc2, g_fc2);

    roi_pool_kernel<<<N_ROIS, CCH>>>(features, rois, pooled);

    // fc1 = pooled @ W0 + b0
    naive_gemm<<<dim3((HID + 255) / 256, N_ROIS / 16), 256>>>(
        pooled, W0, b0, fc1, N_ROIS, HID, IN_FLAT);
    // fc2 = fc1 @ W1 + b1
    naive_gemm<<<dim3((HID + 255) / 256, N_ROIS / 16), 256>>>(
        fc1, W1, b1, fc2, N_ROIS, HID, HID);
    // roi_cls_locs = fc2 @ Wloc + bloc -> out[0 : 256*84)
    naive_gemm<<<dim3(1, N_ROIS / 16), 256>>>(
        fc2, Wloc, bloc, out, N_ROIS, NLOC, HID);
    // roi_scores = fc2 @ Wcls + bcls -> out[256*84 : 26880)
    if (out_size >= N_ROIS * (NLOC + NCLS)) {
        naive_gemm<<<dim3(1, N_ROIS / 16), 256>>>(
            fc2, Wcls, bcls, out + N_ROIS * NLOC, N_ROIS, NCLS, HID);
    }
}

// round 9
// speedup vs baseline: 6.4327x; 6.4327x over previous
#include <cuda_runtime.h>
#include <cuda_bf16.h>
#include <float.h>

#define N_ROIS 256
#define CCH 256
#define HF 50
#define WF 50
#define PK 7
#define IN_FLAT (CCH * PK * PK)   // 12544
#define HID 2048
#define NLOC 84
#define NCLS 21

// Scratch (allocation-free rule: device globals)
__device__ float g_pooled[N_ROIS * IN_FLAT];   // 12.8 MB
__device__ float g_fc1[N_ROIS * HID];          // 2 MB
__device__ float g_fc2[N_ROIS * HID];          // 2 MB

// ---------------------------------------------------------------------------
// RoIPool — FROZEN from R7 pass. __fdividef (div.approx.f32) is LOAD-BEARING:
// it reproduces the XLA:GPU approximate divide the reference was executed
// with. Do NOT "fix" to IEEE divide (that gives rel_err 0.168).
// ---------------------------------------------------------------------------
__global__ void roi_pool_kernel(const float* __restrict__ feat,
                                const float* __restrict__ rois,
                                float* __restrict__ out) {
    int m = blockIdx.x;
    int c = threadIdx.x;

    const float* r = rois + m * 5;
    float x1 = rintf(r[1] * 0.0625f);
    float y1 = rintf(r[2] * 0.0625f);
    float x2 = rintf(r[3] * 0.0625f);
    float y2 = rintf(r[4] * 0.0625f);
    float roi_w = fmaxf(x2 - x1 + 1.0f, 1.0f);
    float roi_h = fmaxf(y2 - y1 + 1.0f, 1.0f);
    float qh = __fdividef(roi_h, 7.0f);   // div.approx.f32 — load-bearing
    float qw = __fdividef(roi_w, 7.0f);   // div.approx.f32 — load-bearing

    const float* fc_ptr = feat + c * (HF * WF);

    for (int ph = 0; ph < PK; ph++) {
        float hs_f = fminf(fmaxf(floorf(__fmul_rn((float)ph, qh)) + y1, 0.0f), (float)HF);
        float he_f = fminf(fmaxf(ceilf(__fmul_rn((float)(ph + 1), qh)) + y1, 0.0f), (float)HF);
        int hs = (int)hs_f, he = (int)he_f;
        for (int pw = 0; pw < PK; pw++) {
            float ws_f = fminf(fmaxf(floorf(__fmul_rn((float)pw, qw)) + x1, 0.0f), (float)WF);
            float we_f = fminf(fmaxf(ceilf(__fmul_rn((float)(pw + 1), qw)) + x1, 0.0f), (float)WF);
            int ws = (int)ws_f, we = (int)we_f;

            float mx;
            if (he <= hs || we <= ws) {
                mx = 0.0f;   // empty bin -> 0
            } else {
                mx = -FLT_MAX;
                for (int h = hs; h < he; h++) {
                    const float* rowp = fc_ptr + h * WF;
                    for (int w = ws; w < we; w++)
                        mx = fmaxf(mx, rowp[w]);
                }
            }
            out[((m * CCH + c) * PK + ph) * PK + pw] = mx;
        }
    }
}

// ---------------------------------------------------------------------------
// Tiled fp32 GEMM: C[M,N] = A[M,K] @ B[K,N] + bias[N]
// 64x64 tile, BK=16, 256 threads, 4x4 per thread.
// Requires: M%64==0, N%64==0, K%16==0, 16B-aligned pointers.
// ---------------------------------------------------------------------------
__global__ void sgemm64(const float* __restrict__ A,
                        const float* __restrict__ B,
                        const float* __restrict__ bias,
                        float* __restrict__ C,
                        int M, int N, int K) {
    __shared__ float As[16][64];   // [k][m]
    __shared__ float Bs[16][64];   // [k][n]

    int t  = threadIdx.x;
    int bn = blockIdx.x * 64;
    int bm = blockIdx.y * 64;
    int tx = t & 15;        // N micro-tile index
    int ty = t >> 4;        // M micro-tile index

    int a_row = t >> 2;             // 0..63
    int a_k4  = (t & 3) * 4;        // 0,4,8,12
    int b_k   = t >> 4;             // 0..15
    int b_n4  = (t & 15) * 4;       // 0..60

    float acc[4][4];
    #pragma unroll
    for (int i = 0; i < 4; i++)
        #pragma unroll
        for (int j = 0; j < 4; j++) acc[i][j] = 0.0f;

    const float* a_ld = A + (long)(bm + a_row) * K + a_k4;
    const float* b_ld = B + (long)b_k * N + bn + b_n4;

    for (int k0 = 0; k0 < K; k0 += 16) {
        float4 av = *(const float4*)(a_ld + k0);
        As[a_k4 + 0][a_row] = av.x;
        As[a_k4 + 1][a_row] = av.y;
        As[a_k4 + 2][a_row] = av.z;
        As[a_k4 + 3][a_row] = av.w;
        float4 bv = *(const float4*)(b_ld + (long)k0 * N);
        *(float4*)&Bs[b_k][b_n4] = bv;
        __syncthreads();

        #pragma unroll
        for (int k = 0; k < 16; k++) {
            float4 a = *(const float4*)&As[k][ty * 4];
            float4 b = *(const float4*)&Bs[k][tx * 4];
            float ar[4] = {a.x, a.y, a.z, a.w};
            float br[4] = {b.x, b.y, b.z, b.w};
            #pragma unroll
            for (int i = 0; i < 4; i++)
                #pragma unroll
                for (int j = 0; j < 4; j++)
                    acc[i][j] = fmaf(ar[i], br[j], acc[i][j]);
        }
        __syncthreads();
    }

    #pragma unroll
    for (int i = 0; i < 4; i++) {
        int row = bm + ty * 4 + i;
        int col = bn + tx * 4;
        float4 bb = *(const float4*)&bias[col];
        float4 o;
        o.x = acc[i][0] + bb.x;
        o.y = acc[i][1] + bb.y;
        o.z = acc[i][2] + bb.z;
        o.w = acc[i][3] + bb.w;
        *(float4*)&C[(long)row * N + col] = o;
    }
}

// ---------------------------------------------------------------------------
// Heads: one block per ROI (256 blocks), fc2 row staged in smem.
// thread t<84 -> loc column, t in [84,105) -> cls column.
// ---------------------------------------------------------------------------
__global__ void heads_kernel(const float* __restrict__ fc,
                             const float* __restrict__ Wloc,
                             const float* __restrict__ bloc,
                             const float* __restrict__ Wcls,
                             const float* __restrict__ bcls,
                             float* __restrict__ out) {
    __shared__ float s_fc[HID];
    int m = blockIdx.x;
    int t = threadIdx.x;   // 128 threads

    for (int k = t; k < HID; k += 128) s_fc[k] = fc[m * HID + k];
    __syncthreads();

    if (t < NLOC) {
        float acc = 0.0f;
        #pragma unroll 4
        for (int k = 0; k < HID; k++)
            acc = fmaf(s_fc[k], Wloc[k * NLOC + t], acc);
        out[m * NLOC + t] = acc + bloc[t];
    } else if (t < NLOC + NCLS) {
        int n = t - NLOC;
        float acc = 0.0f;
        #pragma unroll 4
        for (int k = 0; k < HID; k++)
            acc = fmaf(s_fc[k], Wcls[k * NCLS + n], acc);
        out[N_ROIS * NLOC + m * NCLS + n] = acc + bcls[n];
    }
}

// ---------------------------------------------------------------------------
extern "C" void kernel_launch(void* const* d_in, const int* in_sizes, int n_in,
                              void* d_out, int out_size) {
    // Identify inputs by unique element count (b0/b1 disambiguated by order).
    const float *features = 0, *rois = 0, *W0 = 0, *b0 = 0, *W1 = 0, *b1 = 0,
                *Wcls = 0, *bcls = 0, *Wloc = 0, *bloc = 0;
    for (int i = 0; i < n_in; i++) {
        const float* p = (const float*)d_in[i];
        switch (in_sizes[i]) {
            case 640000:   features = p; break;                 // 1*256*50*50
            case 1280:     rois = p; break;                     // 256*5
            case 25690112: W0 = p; break;                       // 12544*2048
            case 4194304:  W1 = p; break;                       // 2048*2048
            case 43008:    Wcls = p; break;                     // 2048*21
            case 21:       bcls = p; break;
            case 172032:   Wloc = p; break;                     // 2048*84
            case 84:       bloc = p; break;
            case 2048:     if (!b0) b0 = p; else b1 = p; break; // b0 then b1
            default: break;
        }
    }
    float* out = (float*)d_out;

    float* pooled; cudaGetSymbolAddress((void**)&pooled, g_pooled);
    float* fc1;    cudaGetSymbolAddress((void**)&fc1, g_fc1);
    float* fc2;    cudaGetSymbolAddress((void**)&fc2, g_fc2);

    roi_pool_kernel<<<N_ROIS, CCH>>>(features, rois, pooled);

    // fc1 = pooled @ W0 + b0   (256 x 12544) @ (12544 x 2048)
    sgemm64<<<dim3(HID / 64, N_ROIS / 64), 256>>>(pooled, W0, b0, fc1,
                                                  N_ROIS, HID, IN_FLAT);
    // fc2 = fc1 @ W1 + b1      (256 x 2048) @ (2048 x 2048)
    sgemm64<<<dim3(HID / 64, N_ROIS / 64), 256>>>(fc1, W1, b1, fc2,
                                                  N_ROIS, HID, HID);
    // heads -> d_out
    heads_kernel<<<N_ROIS, 128>>>(fc2, Wloc, bloc, Wcls, bcls, out);
}

// round 11
// speedup vs baseline: 13.5526x; 2.1068x over previous
#include <cuda_runtime.h>
#include <cuda_bf16.h>
#include <float.h>

#define N_ROIS 256
#define CCH 256
#define HF 50
#define WF 50
#define HWF (HF * WF)             // 2500
#define PK 7
#define IN_FLAT (CCH * PK * PK)   // 12544
#define HID 2048
#define NLOC 84
#define NCLS 21
#define NHEAD (NLOC + NCLS)       // 105
#define SPLIT1 8                  // GEMM1 K-split (12544/8 = 1568, %16 ok)
#define SPLIT2 2                  // GEMM2 K-split (2048/2 = 1024, %16 ok)

// Scratch (allocation-free rule: device globals)
__device__ float g_featT[HWF * CCH];                 // 2.56 MB (H,W,C)
__device__ float g_pooled[N_ROIS * IN_FLAT];         // 12.8 MB
__device__ float g_fc1[N_ROIS * HID];                // 2 MB
__device__ float g_fc2[N_ROIS * HID];                // 2 MB
__device__ float g_part[SPLIT1 * N_ROIS * HID];      // 16 MB split-K partials

// ---------------------------------------------------------------------------
// Transpose features (C,H,W) -> (H*W, C) for coalesced pooling loads.
// ---------------------------------------------------------------------------
__global__ void transpose_feat(const float* __restrict__ f,
                               float* __restrict__ fT) {
    __shared__ float tile[32][33];
    int hw0 = blockIdx.x * 32;
    int c0  = blockIdx.y * 32;
    int x = threadIdx.x, y = threadIdx.y;   // block (32, 8)

    #pragma unroll
    for (int i = y; i < 32; i += 8) {
        int c = c0 + i, hw = hw0 + x;
        tile[i][x] = (hw < HWF) ? f[c * HWF + hw] : 0.0f;
    }
    __syncthreads();
    #pragma unroll
    for (int i = y; i < 32; i += 8) {
        int hw = hw0 + i, c = c0 + x;
        if (hw < HWF) fT[hw * CCH + c] = tile[x][i];
    }
}

// ---------------------------------------------------------------------------
// RoIPool on transposed features. Bin math FROZEN from R7 pass:
// __fdividef (div.approx.f32) is LOAD-BEARING — matches XLA:GPU's approximate
// divide. Do NOT replace with IEEE divide (rel_err 0.168).
// Thread c reads featT[hw*256 + c]: lanes consecutive -> coalesced.
// ---------------------------------------------------------------------------
__global__ void roi_pool_kernel(const float* __restrict__ featT,
                                const float* __restrict__ rois,
                                float* __restrict__ out) {
    int m = blockIdx.x;
    int c = threadIdx.x;

    const float* r = rois + m * 5;
    float x1 = rintf(r[1] * 0.0625f);
    float y1 = rintf(r[2] * 0.0625f);
    float x2 = rintf(r[3] * 0.0625f);
    float y2 = rintf(r[4] * 0.0625f);
    float roi_w = fmaxf(x2 - x1 + 1.0f, 1.0f);
    float roi_h = fmaxf(y2 - y1 + 1.0f, 1.0f);
    float qh = __fdividef(roi_h, 7.0f);   // load-bearing approx divide
    float qw = __fdividef(roi_w, 7.0f);   // load-bearing approx divide

    for (int ph = 0; ph < PK; ph++) {
        float hs_f = fminf(fmaxf(floorf(__fmul_rn((float)ph, qh)) + y1, 0.0f), (float)HF);
        float he_f = fminf(fmaxf(ceilf(__fmul_rn((float)(ph + 1), qh)) + y1, 0.0f), (float)HF);
        int hs = (int)hs_f, he = (int)he_f;
        for (int pw = 0; pw < PK; pw++) {
            float ws_f = fminf(fmaxf(floorf(__fmul_rn((float)pw, qw)) + x1, 0.0f), (float)WF);
            float we_f = fminf(fmaxf(ceilf(__fmul_rn((float)(pw + 1), qw)) + x1, 0.0f), (float)WF);
            int ws = (int)ws_f, we = (int)we_f;

            float mx;
            if (he <= hs || we <= ws) {
                mx = 0.0f;   // empty bin -> 0
            } else {
                mx = -FLT_MAX;
                for (int h = hs; h < he; h++) {
                    const float* rowp = featT + (h * WF) * CCH + c;
                    for (int w = ws; w < we; w++)
                        mx = fmaxf(mx, rowp[w * CCH]);
                }
            }
            out[((m * CCH + c) * PK + ph) * PK + pw] = mx;
        }
    }
}

// ---------------------------------------------------------------------------
// Split-K tiled fp32 GEMM: Cpart[s] = A[:, sK:(s+1)K) @ B[sK:(s+1)K, :]
// 64x64 tile, BK=16, 256 threads, 4x4 per thread. blockIdx.z = K-slice.
// ---------------------------------------------------------------------------
__global__ void sgemm64_splitk(const float* __restrict__ A,
                               const float* __restrict__ B,
                               float* __restrict__ Cpart,
                               int M, int N, int K, int Kslice) {
    __shared__ float As[16][64];
    __shared__ float Bs[16][64];

    int t  = threadIdx.x;
    int bn = blockIdx.x * 64;
    int bm = blockIdx.y * 64;
    int s  = blockIdx.z;
    int tx = t & 15;
    int ty = t >> 4;

    int a_row = t >> 2;
    int a_k4  = (t & 3) * 4;
    int b_k   = t >> 4;
    int b_n4  = (t & 15) * 4;

    float acc[4][4];
    #pragma unroll
    for (int i = 0; i < 4; i++)
        #pragma unroll
        for (int j = 0; j < 4; j++) acc[i][j] = 0.0f;

    const float* a_ld = A + (long)(bm + a_row) * K + s * Kslice + a_k4;
    const float* b_ld = B + (long)(s * Kslice + b_k) * N + bn + b_n4;

    for (int k0 = 0; k0 < Kslice; k0 += 16) {
        float4 av = *(const float4*)(a_ld + k0);
        As[a_k4 + 0][a_row] = av.x;
        As[a_k4 + 1][a_row] = av.y;
        As[a_k4 + 2][a_row] = av.z;
        As[a_k4 + 3][a_row] = av.w;
        float4 bv = *(const float4*)(b_ld + (long)k0 * N);
        *(float4*)&Bs[b_k][b_n4] = bv;
        __syncthreads();

        #pragma unroll
        for (int k = 0; k < 16; k++) {
            float4 a = *(const float4*)&As[k][ty * 4];
            float4 b = *(const float4*)&Bs[k][tx * 4];
            float ar[4] = {a.x, a.y, a.z, a.w};
            float br[4] = {b.x, b.y, b.z, b.w};
            #pragma unroll
            for (int i = 0; i < 4; i++)
                #pragma unroll
                for (int j = 0; j < 4; j++)
                    acc[i][j] = fmaf(ar[i], br[j], acc[i][j]);
        }
        __syncthreads();
    }

    float* cp = Cpart + (long)s * M * N;
    #pragma unroll
    for (int i = 0; i < 4; i++) {
        int row = bm + ty * 4 + i;
        int col = bn + tx * 4;
        *(float4*)&cp[(long)row * N + col] = *(float4*)&acc[i][0];
    }
}

// ---------------------------------------------------------------------------
// Reduce split-K partials + bias: C[i] = sum_s Cpart[s][i] + bias[i % N]
// ---------------------------------------------------------------------------
__global__ void reduce_bias(const float* __restrict__ Cpart,
                            const float* __restrict__ bias,
                            float* __restrict__ C,
                            int MN, int N, int S) {
    int i = blockIdx.x * blockDim.x + threadIdx.x;
    if (i >= MN) return;
    float acc = 0.0f;
    for (int s = 0; s < S; s++) acc += Cpart[(long)s * MN + i];
    C[i] = acc + bias[i % N];
}

// ---------------------------------------------------------------------------
// Heads: warp-per-output. 256 ROIs x 105 cols = 26880 warps.
// Lane-parallel over K with shfl butterfly reduce; fc2 reads coalesced.
// ---------------------------------------------------------------------------
__global__ void heads_warp(const float* __restrict__ fc,
                           const float* __restrict__ Wloc,
                           const float* __restrict__ bloc,
                           const float* __restrict__ Wcls,
                           const float* __restrict__ bcls,
                           float* __restrict__ out) {
    int warp_id = blockIdx.x * (blockDim.x >> 5) + (threadIdx.x >> 5);
    int lane = threadIdx.x & 31;
    if (warp_id >= N_ROIS * NHEAD) return;
    int m = warp_id / NHEAD;
    int n = warp_id % NHEAD;

    const float* fcr = fc + m * HID;
    float acc = 0.0f;
    if (n < NLOC) {
        #pragma unroll 8
        for (int k = lane; k < HID; k += 32)
            acc = fmaf(fcr[k], Wloc[k * NLOC + n], acc);
    } else {
        int nc = n - NLOC;
        #pragma unroll 8
        for (int k = lane; k < HID; k += 32)
            acc = fmaf(fcr[k], Wcls[k * NCLS + nc], acc);
    }
    #pragma unroll
    for (int o = 16; o > 0; o >>= 1)
        acc += __shfl_xor_sync(0xFFFFFFFFu, acc, o);

    if (lane == 0) {
        if (n < NLOC) out[m * NLOC + n] = acc + bloc[n];
        else          out[N_ROIS * NLOC + m * NCLS + (n - NLOC)] = acc + bcls[n - NLOC];
    }
}

// ---------------------------------------------------------------------------
extern "C" void kernel_launch(void* const* d_in, const int* in_sizes, int n_in,
                              void* d_out, int out_size) {
    // Identify inputs by unique element count (b0/b1 disambiguated by order).
    const float *features = 0, *rois = 0, *W0 = 0, *b0 = 0, *W1 = 0, *b1 = 0,
                *Wcls = 0, *bcls = 0, *Wloc = 0, *bloc = 0;
    for (int i = 0; i < n_in; i++) {
        const float* p = (const float*)d_in[i];
        switch (in_sizes[i]) {
            case 640000:   features = p; break;
            case 1280:     rois = p; break;
            case 25690112: W0 = p; break;
            case 4194304:  W1 = p; break;
            case 43008:    Wcls = p; break;
            case 21:       bcls = p; break;
            case 172032:   Wloc = p; break;
            case 84:       bloc = p; break;
            case 2048:     if (!b0) b0 = p; else b1 = p; break;
            default: break;
        }
    }
    float* out = (float*)d_out;

    float *featT, *pooled, *fc1, *fc2, *part;
    cudaGetSymbolAddress((void**)&featT, g_featT);
    cudaGetSymbolAddress((void**)&pooled, g_pooled);
    cudaGetSymbolAddress((void**)&fc1, g_fc1);
    cudaGetSymbolAddress((void**)&fc2, g_fc2);
    cudaGetSymbolAddress((void**)&part, g_part);

    // 1) transpose features for coalesced pooling
    transpose_feat<<<dim3((HWF + 31) / 32, CCH / 32), dim3(32, 8)>>>(features, featT);
    // 2) RoIPool
    roi_pool_kernel<<<N_ROIS, CCH>>>(featT, rois, pooled);

    // 3) fc1 = pooled @ W0 + b0  (split-K = 8)
    sgemm64_splitk<<<dim3(HID / 64, N_ROIS / 64, SPLIT1), 256>>>(
        pooled, W0, part, N_ROIS, HID, IN_FLAT, IN_FLAT / SPLIT1);
    reduce_bias<<<(N_ROIS * HID + 255) / 256, 256>>>(part, b0, fc1,
                                                     N_ROIS * HID, HID, SPLIT1);
    // 4) fc2 = fc1 @ W1 + b1  (split-K = 2)
    sgemm64_splitk<<<dim3(HID / 64, N_ROIS / 64, SPLIT2), 256>>>(
        fc1, W1, part, N_ROIS, HID, HID, HID / SPLIT2);
    reduce_bias<<<(N_ROIS * HID + 255) / 256, 256>>>(part, b1, fc2,
                                                     N_ROIS * HID, HID, SPLIT2);
    // 5) heads -> d_out  (warp per output)
    heads_warp<<<(N_ROIS * NHEAD * 32 + 255) / 256, 256>>>(
        fc2, Wloc, bloc, Wcls, bcls, out);
}